// round 6
// baseline (speedup 1.0000x reference)
#include <cuda_runtime.h>
#include <cstdint>

#define B_   4
#define N_   4096
#define FIN  256
#define FOUT 128
#define MTOT (B_ * N_)   // 16384

// ---------------- device scratch (no-alloc rule) ----------------
__device__ float g_Wh[(size_t)MTOT * FOUT];   // tf32-rounded values, [row][o]
__device__ float g_src[MTOT];
__device__ float g_dst[MTOT];

// ---------------- helpers ----------------
__device__ __forceinline__ uint32_t f2tf32(float v) {
    uint32_t r;
    asm("cvt.rna.tf32.f32 %0, %1;" : "=r"(r) : "f"(v));
    return r;
}
__device__ __forceinline__ void mma_tf32(float* d, const uint32_t* a, const uint32_t* b) {
    asm volatile(
        "mma.sync.aligned.m16n8k8.row.col.f32.tf32.tf32.f32 "
        "{%0,%1,%2,%3}, {%4,%5,%6,%7}, {%8,%9}, {%0,%1,%2,%3};"
        : "+f"(d[0]), "+f"(d[1]), "+f"(d[2]), "+f"(d[3])
        : "r"(a[0]), "r"(a[1]), "r"(a[2]), "r"(a[3]), "r"(b[0]), "r"(b[1]));
}

// ============================================================
// Kernel 1: Wh = h @ W^T + b ; store tf32-rounded Wh + src/dst
// ============================================================
__global__ void __launch_bounds__(256) k_gemm(
    const float* __restrict__ h, const float* __restrict__ Ww,
    const float* __restrict__ Wb, const float* __restrict__ aw)
{
    __shared__ float hs[32][68];
    __shared__ float ws[32][132];

    const int t  = threadIdx.x;
    const int r0 = blockIdx.x * 64;
    const int to = t & 15, ti = t >> 4;
    const int i0 = ti * 4, o0 = to * 4;

    float acc[4][8];
#pragma unroll
    for (int a = 0; a < 4; a++)
#pragma unroll
        for (int c = 0; c < 8; c++) acc[a][c] = 0.f;

    const int hi = t >> 2, hkb = (t & 3) * 8;
    const int wo = t >> 1, wkb = (t & 1) * 16;

    for (int kt = 0; kt < FIN; kt += 32) {
        const float* hp = h + (size_t)(r0 + hi) * FIN + kt + hkb;
        float4 ha = *(const float4*)(hp);
        float4 hb = *(const float4*)(hp + 4);
        const float* wp = Ww + (size_t)wo * FIN + kt + wkb;
        float4 wa  = *(const float4*)(wp);
        float4 wb4 = *(const float4*)(wp + 4);
        float4 wc  = *(const float4*)(wp + 8);
        float4 wd  = *(const float4*)(wp + 12);

        __syncthreads();

        hs[hkb + 0][hi] = ha.x; hs[hkb + 1][hi] = ha.y;
        hs[hkb + 2][hi] = ha.z; hs[hkb + 3][hi] = ha.w;
        hs[hkb + 4][hi] = hb.x; hs[hkb + 5][hi] = hb.y;
        hs[hkb + 6][hi] = hb.z; hs[hkb + 7][hi] = hb.w;

        ws[wkb +  0][wo] = wa.x;  ws[wkb +  1][wo] = wa.y;
        ws[wkb +  2][wo] = wa.z;  ws[wkb +  3][wo] = wa.w;
        ws[wkb +  4][wo] = wb4.x; ws[wkb +  5][wo] = wb4.y;
        ws[wkb +  6][wo] = wb4.z; ws[wkb +  7][wo] = wb4.w;
        ws[wkb +  8][wo] = wc.x;  ws[wkb +  9][wo] = wc.y;
        ws[wkb + 10][wo] = wc.z;  ws[wkb + 11][wo] = wc.w;
        ws[wkb + 12][wo] = wd.x;  ws[wkb + 13][wo] = wd.y;
        ws[wkb + 14][wo] = wd.z;  ws[wkb + 15][wo] = wd.w;

        __syncthreads();

#pragma unroll 8
        for (int kk = 0; kk < 32; kk++) {
            float4 a4 = *(const float4*)&hs[kk][i0];
            float4 b0 = *(const float4*)&ws[kk][o0];
            float4 b1 = *(const float4*)&ws[kk][o0 + 64];
            float av[4] = {a4.x, a4.y, a4.z, a4.w};
            float bv[8] = {b0.x, b0.y, b0.z, b0.w, b1.x, b1.y, b1.z, b1.w};
#pragma unroll
            for (int ii = 0; ii < 4; ii++)
#pragma unroll
                for (int oo = 0; oo < 8; oo++)
                    acc[ii][oo] = fmaf(av[ii], bv[oo], acc[ii][oo]);
        }
    }

    float bo[8], asv[8], adv[8];
#pragma unroll
    for (int oo = 0; oo < 8; oo++) {
        int o = (oo < 4) ? (o0 + oo) : (64 + o0 + oo - 4);
        bo[oo]  = Wb[o];
        asv[oo] = aw[o];
        adv[oo] = aw[FOUT + o];
    }
    float sp[4], dp[4];
#pragma unroll
    for (int ii = 0; ii < 4; ii++) {
        float s = 0.f, d = 0.f;
        float v[8];
#pragma unroll
        for (int oo = 0; oo < 8; oo++) {
            v[oo] = acc[ii][oo] + bo[oo];
            s = fmaf(v[oo], asv[oo], s);
            d = fmaf(v[oo], adv[oo], d);
        }
        sp[ii] = s; dp[ii] = d;
        const int row = r0 + i0 + ii;
        *(float4*)&g_Wh[(size_t)row * FOUT + o0] =
            make_float4(__uint_as_float(f2tf32(v[0])), __uint_as_float(f2tf32(v[1])),
                        __uint_as_float(f2tf32(v[2])), __uint_as_float(f2tf32(v[3])));
        *(float4*)&g_Wh[(size_t)row * FOUT + 64 + o0] =
            make_float4(__uint_as_float(f2tf32(v[4])), __uint_as_float(f2tf32(v[5])),
                        __uint_as_float(f2tf32(v[6])), __uint_as_float(f2tf32(v[7])));
    }
#pragma unroll
    for (int off = 8; off >= 1; off >>= 1)
#pragma unroll
        for (int ii = 0; ii < 4; ii++) {
            sp[ii] += __shfl_down_sync(0xffffffffu, sp[ii], off);
            dp[ii] += __shfl_down_sync(0xffffffffu, dp[ii], off);
        }
    if (to == 0)
#pragma unroll
        for (int ii = 0; ii < 4; ii++) {
            g_src[r0 + i0 + ii] = sp[ii];
            g_dst[r0 + i0 + ii] = dp[ii];
        }
}

// ============================================================
// Kernel 2: attention via warp-level tf32 mma.sync.
// CTA: 128 rows x 128 cols, K-chunks of 64, 8 warps of 64x32 tiles.
// Double-buffered A/B smem, single __syncthreads per chunk:
//   iter c: LDG(c+1) -> MMA(buf c) -> exp/cvt/STS(buf c^1) -> sync
// ============================================================
#define KC     64
#define STRD   136                        // smem row stride (floats)
#define ABYTES (KC * STRD * 4)            // 34816
#define SM_DST 0                          // 4096 f = 16384 B
#define SM_DEN 16384                      // 256 f
#define SM_A0  17408
#define SM_A1  (SM_A0 + ABYTES)
#define SM_B0  (SM_A1 + ABYTES)
#define SM_B1  (SM_B0 + ABYTES)
#define SMEM_SZ (SM_B1 + ABYTES)          // 156672

__global__ void __launch_bounds__(256, 1) k_attn(
    const int* __restrict__ adj, const float* __restrict__ abp,
    float* __restrict__ out)
{
    extern __shared__ char sm[];
    float*    dst_s = (float*)(sm + SM_DST);
    float*    den_s = (float*)(sm + SM_DEN);
    uint32_t* Abuf[2] = { (uint32_t*)(sm + SM_A0), (uint32_t*)(sm + SM_A1) };
    uint32_t* Bbuf[2] = { (uint32_t*)(sm + SM_B0), (uint32_t*)(sm + SM_B1) };

    const int t   = threadIdx.x;
    const int rg0 = blockIdx.x * 128;
    const int b   = rg0 >> 12;
    const int bN  = b << 12;

    // stage dst for this batch
    {
        const float4* g  = (const float4*)(g_dst + bN);
        float4*       d4 = (float4*)dst_s;
        for (int q = t; q < N_ / 4; q += 256) d4[q] = g[q];
    }

    // producer mapping: thread t -> row i, j-half
    const int i    = t & 127;
    const int half = t >> 7;               // 0/1 -> j offset 0/32
    const float srcA = g_src[rg0 + i] + *abp;
    const int4* adjp = (const int4*)(adj + (size_t)(rg0 + i) * N_ + half * 32);

    // B copy mapping: thread t -> Wh row (t>>2), float4 cols (t&3)+4q
    const int bj = t >> 2, bc = t & 3;
    const float4* whp = (const float4*)(g_Wh + (size_t)(bN + bj) * FOUT) + bc;

    // mma mapping: 8 warps, 2x4 grid of 64x32 tiles
    const int w = t >> 5, lane = t & 31;
    const int m0 = (w >> 2) * 64, n0 = (w & 3) * 32;
    const int lr = lane >> 2, lq = lane & 3;

    float acc[16][4];
#pragma unroll
    for (int x = 0; x < 16; x++)
#pragma unroll
        for (int y = 0; y < 4; y++) acc[x][y] = 0.f;
    float denp = 0.f;

    __syncthreads();   // dst_s ready

    // ---------- produce chunk 0 into buf 0 ----------
    {
        int4   mA[8];
        float4 vB[8];
#pragma unroll
        for (int q = 0; q < 8; q++) mA[q] = adjp[q];
#pragma unroll
        for (int q = 0; q < 8; q++) vB[q] = whp[q * 4];
        uint32_t* As = Abuf[0];
        uint32_t* Bs = Bbuf[0];
#pragma unroll
        for (int q = 0; q < 8; q++) {
            float4 dv = *(const float4*)&dst_s[half * 32 + q * 4];
            int4 m = mA[q];
            float e0 = srcA + dv.x, e1 = srcA + dv.y, e2 = srcA + dv.z, e3 = srcA + dv.w;
            e0 = (e0 >= 0.f) ? e0 : 0.01f * e0;
            e1 = (e1 >= 0.f) ? e1 : 0.01f * e1;
            e2 = (e2 >= 0.f) ? e2 : 0.01f * e2;
            e3 = (e3 >= 0.f) ? e3 : 0.01f * e3;
            float w0 = (m.x > 0) ? __expf(e0) : 0.f;
            float w1 = (m.y > 0) ? __expf(e1) : 0.f;
            float w2 = (m.z > 0) ? __expf(e2) : 0.f;
            float w3 = (m.w > 0) ? __expf(e3) : 0.f;
            denp += (w0 + w1) + (w2 + w3);
            int k0 = half * 32 + q * 4;
            As[(k0 + 0) * STRD + i] = f2tf32(w0);
            As[(k0 + 1) * STRD + i] = f2tf32(w1);
            As[(k0 + 2) * STRD + i] = f2tf32(w2);
            As[(k0 + 3) * STRD + i] = f2tf32(w3);
        }
#pragma unroll
        for (int q = 0; q < 8; q++)
            *(float4*)&Bs[bj * STRD + (bc + 4 * q) * 4] = vB[q];
    }
    __syncthreads();

    // ---------- pipelined main loop ----------
    for (int c = 0; c < N_ / KC; c++) {
        const int buf = c & 1;
        const bool more = (c < N_ / KC - 1);

        // 1) issue LDGs for chunk c+1 (land during MMA phase)
        int4   mA[8];
        float4 vB[8];
        if (more) {
#pragma unroll
            for (int q = 0; q < 8; q++) mA[q] = adjp[(c + 1) * 16 + q];
#pragma unroll
            for (int q = 0; q < 8; q++) vB[q] = whp[(size_t)(c + 1) * KC * (FOUT / 4) + q * 4];
        }

        // 2) MMA on buffer c
        {
            const uint32_t* As = Abuf[buf];
            const uint32_t* Bs = Bbuf[buf];
#pragma unroll
            for (int kk = 0; kk < 8; kk++) {
                uint32_t bf[4][2];
#pragma unroll
                for (int nt = 0; nt < 4; nt++) {
                    int o = n0 + nt * 8 + lr;
                    bf[nt][0] = Bs[(kk * 8 + lq) * STRD + o];
                    bf[nt][1] = Bs[(kk * 8 + lq + 4) * STRD + o];
                }
#pragma unroll
                for (int mt = 0; mt < 4; mt++) {
                    uint32_t af[4];
                    int m = m0 + mt * 16 + lr;
                    af[0] = As[(kk * 8 + lq) * STRD + m];
                    af[1] = As[(kk * 8 + lq) * STRD + m + 8];
                    af[2] = As[(kk * 8 + lq + 4) * STRD + m];
                    af[3] = As[(kk * 8 + lq + 4) * STRD + m + 8];
#pragma unroll
                    for (int nt = 0; nt < 4; nt++)
                        mma_tf32(acc[mt * 4 + nt], af, bf[nt]);
                }
            }
        }

        // 3) produce chunk c+1 into the other buffer
        if (more) {
            uint32_t* As = Abuf[buf ^ 1];
            uint32_t* Bs = Bbuf[buf ^ 1];
#pragma unroll
            for (int q = 0; q < 8; q++) {
                float4 dv = *(const float4*)&dst_s[(c + 1) * KC + half * 32 + q * 4];
                int4 m = mA[q];
                float e0 = srcA + dv.x, e1 = srcA + dv.y, e2 = srcA + dv.z, e3 = srcA + dv.w;
                e0 = (e0 >= 0.f) ? e0 : 0.01f * e0;
                e1 = (e1 >= 0.f) ? e1 : 0.01f * e1;
                e2 = (e2 >= 0.f) ? e2 : 0.01f * e2;
                e3 = (e3 >= 0.f) ? e3 : 0.01f * e3;
                float w0 = (m.x > 0) ? __expf(e0) : 0.f;
                float w1 = (m.y > 0) ? __expf(e1) : 0.f;
                float w2 = (m.z > 0) ? __expf(e2) : 0.f;
                float w3 = (m.w > 0) ? __expf(e3) : 0.f;
                denp += (w0 + w1) + (w2 + w3);
                int k0 = half * 32 + q * 4;
                As[(k0 + 0) * STRD + i] = f2tf32(w0);
                As[(k0 + 1) * STRD + i] = f2tf32(w1);
                As[(k0 + 2) * STRD + i] = f2tf32(w2);
                As[(k0 + 3) * STRD + i] = f2tf32(w3);
            }
#pragma unroll
            for (int q = 0; q < 8; q++)
                *(float4*)&Bs[bj * STRD + (bc + 4 * q) * 4] = vB[q];
        }

        __syncthreads();
    }

    den_s[t] = denp;
    __syncthreads();

    // ---- epilogue: divide by den, store ----
#pragma unroll
    for (int mt = 0; mt < 4; mt++) {
        int r0 = m0 + mt * 16 + lr;
        float inv0 = 1.0f / (den_s[r0] + den_s[r0 + 128]);
        float inv1 = 1.0f / (den_s[r0 + 8] + den_s[r0 + 8 + 128]);
        float* op0 = out + (size_t)(rg0 + r0) * FOUT;
        float* op1 = out + (size_t)(rg0 + r0 + 8) * FOUT;
#pragma unroll
        for (int nt = 0; nt < 4; nt++) {
            int col = n0 + nt * 8 + lq * 2;
            *(float2*)(op0 + col) = make_float2(acc[mt * 4 + nt][0] * inv0,
                                                acc[mt * 4 + nt][1] * inv0);
            *(float2*)(op1 + col) = make_float2(acc[mt * 4 + nt][2] * inv1,
                                                acc[mt * 4 + nt][3] * inv1);
        }
    }
}

extern "C" void kernel_launch(void* const* d_in, const int* in_sizes, int n_in,
                              void* d_out, int out_size) {
    const float* h   = (const float*)d_in[0];
    const int*   adj = (const int*)d_in[1];
    const float* Ww  = (const float*)d_in[2];
    const float* Wb  = (const float*)d_in[3];
    const float* aw  = (const float*)d_in[4];
    const float* abp = (const float*)d_in[5];
    float* outp = (float*)d_out;

    cudaFuncSetAttribute(k_attn, cudaFuncAttributeMaxDynamicSharedMemorySize, SMEM_SZ);

    k_gemm<<<MTOT / 64, 256>>>(h, Ww, Wb, aw);
    k_attn<<<MTOT / 128, 256, SMEM_SZ>>>(adj, abp, outp);
}

// round 7
// speedup vs baseline: 1.0445x; 1.0445x over previous
#include <cuda_runtime.h>
#include <cstdint>

#define B_   4
#define N_   4096
#define FIN  256
#define FOUT 128
#define MTOT (B_ * N_)   // 16384

// ---------------- device scratch (no-alloc rule) ----------------
__device__ float g_Wh[(size_t)MTOT * FOUT];   // tf32-rounded values, [row][o]
__device__ float g_src[MTOT];
__device__ float g_dst[MTOT];

// ---------------- helpers ----------------
__device__ __forceinline__ uint32_t f2tf32(float v) {
    uint32_t r;
    asm("cvt.rna.tf32.f32 %0, %1;" : "=r"(r) : "f"(v));
    return r;
}
__device__ __forceinline__ void mma_tf32(float* d, const uint32_t* a, const uint32_t* b) {
    asm volatile(
        "mma.sync.aligned.m16n8k8.row.col.f32.tf32.tf32.f32 "
        "{%0,%1,%2,%3}, {%4,%5,%6,%7}, {%8,%9}, {%0,%1,%2,%3};"
        : "+f"(d[0]), "+f"(d[1]), "+f"(d[2]), "+f"(d[3])
        : "r"(a[0]), "r"(a[1]), "r"(a[2]), "r"(a[3]), "r"(b[0]), "r"(b[1]));
}

// ============================================================
// Kernel 1: Wh = h @ W^T + b ; store tf32-rounded Wh + src/dst
// ============================================================
__global__ void __launch_bounds__(256) k_gemm(
    const float* __restrict__ h, const float* __restrict__ Ww,
    const float* __restrict__ Wb, const float* __restrict__ aw)
{
    __shared__ float hs[32][68];
    __shared__ float ws[32][132];

    const int t  = threadIdx.x;
    const int r0 = blockIdx.x * 64;
    const int to = t & 15, ti = t >> 4;
    const int i0 = ti * 4, o0 = to * 4;

    float acc[4][8];
#pragma unroll
    for (int a = 0; a < 4; a++)
#pragma unroll
        for (int c = 0; c < 8; c++) acc[a][c] = 0.f;

    const int hi = t >> 2, hkb = (t & 3) * 8;
    const int wo = t >> 1, wkb = (t & 1) * 16;

    for (int kt = 0; kt < FIN; kt += 32) {
        const float* hp = h + (size_t)(r0 + hi) * FIN + kt + hkb;
        float4 ha = *(const float4*)(hp);
        float4 hb = *(const float4*)(hp + 4);
        const float* wp = Ww + (size_t)wo * FIN + kt + wkb;
        float4 wa  = *(const float4*)(wp);
        float4 wb4 = *(const float4*)(wp + 4);
        float4 wc  = *(const float4*)(wp + 8);
        float4 wd  = *(const float4*)(wp + 12);

        __syncthreads();

        hs[hkb + 0][hi] = ha.x; hs[hkb + 1][hi] = ha.y;
        hs[hkb + 2][hi] = ha.z; hs[hkb + 3][hi] = ha.w;
        hs[hkb + 4][hi] = hb.x; hs[hkb + 5][hi] = hb.y;
        hs[hkb + 6][hi] = hb.z; hs[hkb + 7][hi] = hb.w;

        ws[wkb +  0][wo] = wa.x;  ws[wkb +  1][wo] = wa.y;
        ws[wkb +  2][wo] = wa.z;  ws[wkb +  3][wo] = wa.w;
        ws[wkb +  4][wo] = wb4.x; ws[wkb +  5][wo] = wb4.y;
        ws[wkb +  6][wo] = wb4.z; ws[wkb +  7][wo] = wb4.w;
        ws[wkb +  8][wo] = wc.x;  ws[wkb +  9][wo] = wc.y;
        ws[wkb + 10][wo] = wc.z;  ws[wkb + 11][wo] = wc.w;
        ws[wkb + 12][wo] = wd.x;  ws[wkb + 13][wo] = wd.y;
        ws[wkb + 14][wo] = wd.z;  ws[wkb + 15][wo] = wd.w;

        __syncthreads();

#pragma unroll 8
        for (int kk = 0; kk < 32; kk++) {
            float4 a4 = *(const float4*)&hs[kk][i0];
            float4 b0 = *(const float4*)&ws[kk][o0];
            float4 b1 = *(const float4*)&ws[kk][o0 + 64];
            float av[4] = {a4.x, a4.y, a4.z, a4.w};
            float bv[8] = {b0.x, b0.y, b0.z, b0.w, b1.x, b1.y, b1.z, b1.w};
#pragma unroll
            for (int ii = 0; ii < 4; ii++)
#pragma unroll
                for (int oo = 0; oo < 8; oo++)
                    acc[ii][oo] = fmaf(av[ii], bv[oo], acc[ii][oo]);
        }
    }

    float bo[8], asv[8], adv[8];
#pragma unroll
    for (int oo = 0; oo < 8; oo++) {
        int o = (oo < 4) ? (o0 + oo) : (64 + o0 + oo - 4);
        bo[oo]  = Wb[o];
        asv[oo] = aw[o];
        adv[oo] = aw[FOUT + o];
    }
    float sp[4], dp[4];
#pragma unroll
    for (int ii = 0; ii < 4; ii++) {
        float s = 0.f, d = 0.f;
        float v[8];
#pragma unroll
        for (int oo = 0; oo < 8; oo++) {
            v[oo] = acc[ii][oo] + bo[oo];
            s = fmaf(v[oo], asv[oo], s);
            d = fmaf(v[oo], adv[oo], d);
        }
        sp[ii] = s; dp[ii] = d;
        const int row = r0 + i0 + ii;
        *(float4*)&g_Wh[(size_t)row * FOUT + o0] =
            make_float4(__uint_as_float(f2tf32(v[0])), __uint_as_float(f2tf32(v[1])),
                        __uint_as_float(f2tf32(v[2])), __uint_as_float(f2tf32(v[3])));
        *(float4*)&g_Wh[(size_t)row * FOUT + 64 + o0] =
            make_float4(__uint_as_float(f2tf32(v[4])), __uint_as_float(f2tf32(v[5])),
                        __uint_as_float(f2tf32(v[6])), __uint_as_float(f2tf32(v[7])));
    }
#pragma unroll
    for (int off = 8; off >= 1; off >>= 1)
#pragma unroll
        for (int ii = 0; ii < 4; ii++) {
            sp[ii] += __shfl_down_sync(0xffffffffu, sp[ii], off);
            dp[ii] += __shfl_down_sync(0xffffffffu, dp[ii], off);
        }
    if (to == 0)
#pragma unroll
        for (int ii = 0; ii < 4; ii++) {
            g_src[r0 + i0 + ii] = sp[ii];
            g_dst[r0 + i0 + ii] = dp[ii];
        }
}

// ============================================================
// Kernel 2: attention via warp-level tf32 mma.sync.
// CTA: 128 rows x 128 cols, 512 threads / 16 warps (32x32 warp tiles),
// K-chunks of 64, single-buffer, two syncs per chunk (R4 structure).
// ============================================================
#define KC     64
#define STRD   136                        // smem row stride (floats)
#define ABYTES (KC * STRD * 4)            // 34816
#define SM_DST 0                          // 4096 f = 16384 B
#define SM_DEN 16384                      // 512 f = 2048 B
#define SM_A   18432
#define SM_B   (SM_A + ABYTES)
#define SMEM_SZ (SM_B + ABYTES)           // 88064

__global__ void __launch_bounds__(512, 1) k_attn(
    const int* __restrict__ adj, const float* __restrict__ abp,
    float* __restrict__ out)
{
    extern __shared__ char sm[];
    float*    dst_s = (float*)(sm + SM_DST);
    float*    den_s = (float*)(sm + SM_DEN);   // [4][128]
    uint32_t* As    = (uint32_t*)(sm + SM_A);
    uint32_t* Bs    = (uint32_t*)(sm + SM_B);

    const int t   = threadIdx.x;
    const int rg0 = blockIdx.x * 128;
    const int b   = rg0 >> 12;
    const int bN  = b << 12;

    // stage dst for this batch (4096 floats, 512 threads -> 2 float4 each)
    {
        const float4* g  = (const float4*)(g_dst + bN);
        float4*       d4 = (float4*)dst_s;
        for (int q = t; q < N_ / 4; q += 512) d4[q] = g[q];
    }

    // producer mapping: thread -> row i, j-quarter q4 (16 j's)
    const int i  = t & 127;
    const int q4 = t >> 7;                 // 0..3
    const float srcA = g_src[rg0 + i] + *abp;
    const int4* adjp = (const int4*)(adj + (size_t)(rg0 + i) * N_ + q4 * 16);

    // B copy mapping: thread -> Wh row bj (0..63), float4 col bc (0..7)
    const int bj = t >> 3, bc = t & 7;
    const float4* whp = (const float4*)(g_Wh + (size_t)(bN + bj) * FOUT) + bc;

    // mma mapping: 16 warps, 4x4 grid of 32x32 tiles
    const int w = t >> 5, lane = t & 31;
    const int m0 = (w >> 2) * 32, n0 = (w & 3) * 32;
    const int lr = lane >> 2, lq = lane & 3;

    float acc[8][4];
#pragma unroll
    for (int x = 0; x < 8; x++)
#pragma unroll
        for (int y = 0; y < 4; y++) acc[x][y] = 0.f;
    float denp = 0.f;

    // prefetch chunk 0
    int4   mA[4];
    float4 vB[4];
#pragma unroll
    for (int q = 0; q < 4; q++) mA[q] = adjp[q];
#pragma unroll
    for (int q = 0; q < 4; q++) vB[q] = whp[q * 8];

    __syncthreads();   // dst_s ready

    for (int c = 0; c < N_ / KC; c++) {
        // ---- weights: exp(lrelu(src+dst+ab)), masked; den in fp32 ----
        uint32_t wv[16];
#pragma unroll
        for (int q = 0; q < 4; q++) {
            float4 dv = *(const float4*)&dst_s[c * KC + q4 * 16 + q * 4];
            int4 m = mA[q];
            float e0 = srcA + dv.x, e1 = srcA + dv.y, e2 = srcA + dv.z, e3 = srcA + dv.w;
            e0 = (e0 >= 0.f) ? e0 : 0.01f * e0;
            e1 = (e1 >= 0.f) ? e1 : 0.01f * e1;
            e2 = (e2 >= 0.f) ? e2 : 0.01f * e2;
            e3 = (e3 >= 0.f) ? e3 : 0.01f * e3;
            float w0 = (m.x > 0) ? __expf(e0) : 0.f;
            float w1 = (m.y > 0) ? __expf(e1) : 0.f;
            float w2 = (m.z > 0) ? __expf(e2) : 0.f;
            float w3 = (m.w > 0) ? __expf(e3) : 0.f;
            denp += (w0 + w1) + (w2 + w3);
            wv[q * 4 + 0] = f2tf32(w0);
            wv[q * 4 + 1] = f2tf32(w1);
            wv[q * 4 + 2] = f2tf32(w2);
            wv[q * 4 + 3] = f2tf32(w3);
        }

        __syncthreads();   // previous chunk's mma reads done

        // ---- store A (weights) [k][m] and B (Wh) [k][o] ----
#pragma unroll
        for (int q = 0; q < 4; q++) {
            int k0 = q4 * 16 + q * 4;
            As[(k0 + 0) * STRD + i] = wv[q * 4 + 0];
            As[(k0 + 1) * STRD + i] = wv[q * 4 + 1];
            As[(k0 + 2) * STRD + i] = wv[q * 4 + 2];
            As[(k0 + 3) * STRD + i] = wv[q * 4 + 3];
        }
#pragma unroll
        for (int q = 0; q < 4; q++)
            *(float4*)&Bs[bj * STRD + (bc + 8 * q) * 4] = vB[q];

        // ---- prefetch next chunk (lands during mma) ----
        if (c < N_ / KC - 1) {
#pragma unroll
            for (int q = 0; q < 4; q++) mA[q] = adjp[(c + 1) * 16 + q];
#pragma unroll
            for (int q = 0; q < 4; q++) vB[q] = whp[(size_t)(c + 1) * KC * (FOUT / 4) + q * 8];
        }

        __syncthreads();

        // ---- mma: 8 k-steps of m16n8k8, 32x32 warp tile ----
#pragma unroll
        for (int kk = 0; kk < 8; kk++) {
            uint32_t bf[4][2];
#pragma unroll
            for (int nt = 0; nt < 4; nt++) {
                int o = n0 + nt * 8 + lr;
                bf[nt][0] = Bs[(kk * 8 + lq) * STRD + o];
                bf[nt][1] = Bs[(kk * 8 + lq + 4) * STRD + o];
            }
#pragma unroll
            for (int mt = 0; mt < 2; mt++) {
                uint32_t af[4];
                int m = m0 + mt * 16 + lr;
                af[0] = As[(kk * 8 + lq) * STRD + m];
                af[1] = As[(kk * 8 + lq) * STRD + m + 8];
                af[2] = As[(kk * 8 + lq + 4) * STRD + m];
                af[3] = As[(kk * 8 + lq + 4) * STRD + m + 8];
#pragma unroll
                for (int nt = 0; nt < 4; nt++)
                    mma_tf32(acc[mt * 4 + nt], af, bf[nt]);
            }
        }
    }

    den_s[q4 * 128 + i] = denp;
    __syncthreads();

    // ---- epilogue: divide by den, store ----
#pragma unroll
    for (int mt = 0; mt < 2; mt++) {
        int r0 = m0 + mt * 16 + lr;
        float inv0 = 1.0f / (((den_s[r0] + den_s[r0 + 128]) +
                              (den_s[r0 + 256] + den_s[r0 + 384])));
        int r1 = r0 + 8;
        float inv1 = 1.0f / (((den_s[r1] + den_s[r1 + 128]) +
                              (den_s[r1 + 256] + den_s[r1 + 384])));
        float* op0 = out + (size_t)(rg0 + r0) * FOUT;
        float* op1 = out + (size_t)(rg0 + r1) * FOUT;
#pragma unroll
        for (int nt = 0; nt < 4; nt++) {
            int col = n0 + nt * 8 + lq * 2;
            *(float2*)(op0 + col) = make_float2(acc[mt * 4 + nt][0] * inv0,
                                                acc[mt * 4 + nt][1] * inv0);
            *(float2*)(op1 + col) = make_float2(acc[mt * 4 + nt][2] * inv1,
                                                acc[mt * 4 + nt][3] * inv1);
        }
    }
}

extern "C" void kernel_launch(void* const* d_in, const int* in_sizes, int n_in,
                              void* d_out, int out_size) {
    const float* h   = (const float*)d_in[0];
    const int*   adj = (const int*)d_in[1];
    const float* Ww  = (const float*)d_in[2];
    const float* Wb  = (const float*)d_in[3];
    const float* aw  = (const float*)d_in[4];
    const float* abp = (const float*)d_in[5];
    float* outp = (float*)d_out;

    cudaFuncSetAttribute(k_attn, cudaFuncAttributeMaxDynamicSharedMemorySize, SMEM_SZ);

    k_gemm<<<MTOT / 64, 256>>>(h, Ww, Wb, aw);
    k_attn<<<MTOT / 128, 512, SMEM_SZ>>>(adj, abp, outp);
}

// round 9
// speedup vs baseline: 1.3154x; 1.2593x over previous
#include <cuda_runtime.h>
#include <cstdint>

#define B_   4
#define N_   4096
#define FIN  256
#define FOUT 128
#define MTOT (B_ * N_)   // 16384

// ---------------- device scratch (no-alloc rule) ----------------
__device__ float g_Wh[(size_t)MTOT * FOUT];   // tf32-rounded values, [row][o]
__device__ float g_src[MTOT];
__device__ float g_dst[MTOT];

// ---------------- helpers ----------------
__device__ __forceinline__ uint32_t f2tf32(float v) {
    uint32_t r;
    asm("cvt.rna.tf32.f32 %0, %1;" : "=r"(r) : "f"(v));
    return r;
}
__device__ __forceinline__ void mma_tf32(float* d, const uint32_t* a, const uint32_t* b) {
    asm volatile(
        "mma.sync.aligned.m16n8k8.row.col.f32.tf32.tf32.f32 "
        "{%0,%1,%2,%3}, {%4,%5,%6,%7}, {%8,%9}, {%0,%1,%2,%3};"
        : "+f"(d[0]), "+f"(d[1]), "+f"(d[2]), "+f"(d[3])
        : "r"(a[0]), "r"(a[1]), "r"(a[2]), "r"(a[3]), "r"(b[0]), "r"(b[1]));
}

// ============================================================
// Kernel 1: Wh = h @ W^T + b ; store tf32-rounded Wh + src/dst
// ============================================================
__global__ void __launch_bounds__(256) k_gemm(
    const float* __restrict__ h, const float* __restrict__ Ww,
    const float* __restrict__ Wb, const float* __restrict__ aw)
{
    __shared__ float hs[32][68];
    __shared__ float ws[32][132];

    const int t  = threadIdx.x;
    const int r0 = blockIdx.x * 64;
    const int to = t & 15, ti = t >> 4;
    const int i0 = ti * 4, o0 = to * 4;

    float acc[4][8];
#pragma unroll
    for (int a = 0; a < 4; a++)
#pragma unroll
        for (int c = 0; c < 8; c++) acc[a][c] = 0.f;

    const int hi = t >> 2, hkb = (t & 3) * 8;
    const int wo = t >> 1, wkb = (t & 1) * 16;

    for (int kt = 0; kt < FIN; kt += 32) {
        const float* hp = h + (size_t)(r0 + hi) * FIN + kt + hkb;
        float4 ha = *(const float4*)(hp);
        float4 hb = *(const float4*)(hp + 4);
        const float* wp = Ww + (size_t)wo * FIN + kt + wkb;
        float4 wa  = *(const float4*)(wp);
        float4 wb4 = *(const float4*)(wp + 4);
        float4 wc  = *(const float4*)(wp + 8);
        float4 wd  = *(const float4*)(wp + 12);

        __syncthreads();

        hs[hkb + 0][hi] = ha.x; hs[hkb + 1][hi] = ha.y;
        hs[hkb + 2][hi] = ha.z; hs[hkb + 3][hi] = ha.w;
        hs[hkb + 4][hi] = hb.x; hs[hkb + 5][hi] = hb.y;
        hs[hkb + 6][hi] = hb.z; hs[hkb + 7][hi] = hb.w;

        ws[wkb +  0][wo] = wa.x;  ws[wkb +  1][wo] = wa.y;
        ws[wkb +  2][wo] = wa.z;  ws[wkb +  3][wo] = wa.w;
        ws[wkb +  4][wo] = wb4.x; ws[wkb +  5][wo] = wb4.y;
        ws[wkb +  6][wo] = wb4.z; ws[wkb +  7][wo] = wb4.w;
        ws[wkb +  8][wo] = wc.x;  ws[wkb +  9][wo] = wc.y;
        ws[wkb + 10][wo] = wc.z;  ws[wkb + 11][wo] = wc.w;
        ws[wkb + 12][wo] = wd.x;  ws[wkb + 13][wo] = wd.y;
        ws[wkb + 14][wo] = wd.z;  ws[wkb + 15][wo] = wd.w;

        __syncthreads();

#pragma unroll 8
        for (int kk = 0; kk < 32; kk++) {
            float4 a4 = *(const float4*)&hs[kk][i0];
            float4 b0 = *(const float4*)&ws[kk][o0];
            float4 b1 = *(const float4*)&ws[kk][o0 + 64];
            float av[4] = {a4.x, a4.y, a4.z, a4.w};
            float bv[8] = {b0.x, b0.y, b0.z, b0.w, b1.x, b1.y, b1.z, b1.w};
#pragma unroll
            for (int ii = 0; ii < 4; ii++)
#pragma unroll
                for (int oo = 0; oo < 8; oo++)
                    acc[ii][oo] = fmaf(av[ii], bv[oo], acc[ii][oo]);
        }
    }

    float bo[8], asv[8], adv[8];
#pragma unroll
    for (int oo = 0; oo < 8; oo++) {
        int o = (oo < 4) ? (o0 + oo) : (64 + o0 + oo - 4);
        bo[oo]  = Wb[o];
        asv[oo] = aw[o];
        adv[oo] = aw[FOUT + o];
    }
    float sp[4], dp[4];
#pragma unroll
    for (int ii = 0; ii < 4; ii++) {
        float s = 0.f, d = 0.f;
        float v[8];
#pragma unroll
        for (int oo = 0; oo < 8; oo++) {
            v[oo] = acc[ii][oo] + bo[oo];
            s = fmaf(v[oo], asv[oo], s);
            d = fmaf(v[oo], adv[oo], d);
        }
        sp[ii] = s; dp[ii] = d;
        const int row = r0 + i0 + ii;
        *(float4*)&g_Wh[(size_t)row * FOUT + o0] =
            make_float4(__uint_as_float(f2tf32(v[0])), __uint_as_float(f2tf32(v[1])),
                        __uint_as_float(f2tf32(v[2])), __uint_as_float(f2tf32(v[3])));
        *(float4*)&g_Wh[(size_t)row * FOUT + 64 + o0] =
            make_float4(__uint_as_float(f2tf32(v[4])), __uint_as_float(f2tf32(v[5])),
                        __uint_as_float(f2tf32(v[6])), __uint_as_float(f2tf32(v[7])));
    }
#pragma unroll
    for (int off = 8; off >= 1; off >>= 1)
#pragma unroll
        for (int ii = 0; ii < 4; ii++) {
            sp[ii] += __shfl_down_sync(0xffffffffu, sp[ii], off);
            dp[ii] += __shfl_down_sync(0xffffffffu, dp[ii], off);
        }
    if (to == 0)
#pragma unroll
        for (int ii = 0; ii < 4; ii++) {
            g_src[r0 + i0 + ii] = sp[ii];
            g_dst[r0 + i0 + ii] = dp[ii];
        }
}

// ============================================================
// Kernel 2: attention via warp-level tf32 mma.sync.
// CTA: 128 rows x 128 cols, 512 threads / 16 warps (32x32 MMA tiles).
// Producer: warp w owns rows w*8..w*8+7, lane owns cols (2*lane, 2*lane+1)
//   -> adj LDG.64 fully coalesced; A tile [m][k] stride 68 (conflict-free).
// ============================================================
#define KC     64
#define STRA   68                         // A tile stride (floats): 68 % 32 == 4
#define STRB   136                        // B tile stride (floats)
#define SM_DST 0                          // 4096 f = 16384 B
#define SM_DEN 16384                      // 128 f
#define SM_A   17408                      // 128*STRA f = 34816 B
#define SM_B   (SM_A + 128 * STRA * 4)
#define SMEM_SZ (SM_B + KC * STRB * 4)    // 87040

__global__ void __launch_bounds__(512, 1) k_attn(
    const int* __restrict__ adj, const float* __restrict__ abp,
    float* __restrict__ out)
{
    extern __shared__ char sm[];
    float*    dst_s = (float*)(sm + SM_DST);
    float*    den_s = (float*)(sm + SM_DEN);
    uint32_t* As    = (uint32_t*)(sm + SM_A);   // [m][k], stride STRA
    uint32_t* Bs    = (uint32_t*)(sm + SM_B);   // [k][o], stride STRB

    const int t    = threadIdx.x;
    const int w    = t >> 5, lane = t & 31;
    const int rg0  = blockIdx.x * 128;
    const int b    = rg0 >> 12;
    const int bN   = b << 12;
    const int wr0  = w * 8;                 // this warp's 8 rows
    const int cl   = 2 * lane;              // this lane's 2 cols per chunk

    // stage dst for this batch
    {
        const float4* g  = (const float4*)(g_dst + bN);
        float4*       d4 = (float4*)dst_s;
        for (int q = t; q < N_ / 4; q += 512) d4[q] = g[q];
    }

    // per-row src (+bias), adj row pointers
    const float ab = *abp;
    float srcA[8];
#pragma unroll
    for (int rr = 0; rr < 8; rr++) srcA[rr] = g_src[rg0 + wr0 + rr] + ab;

    // B copy mapping: thread -> Wh row bj (0..63), float4 col bc (0..7)
    const int bj = t >> 3, bc = t & 7;
    const float4* whp = (const float4*)(g_Wh + (size_t)(bN + bj) * FOUT) + bc;

    // mma mapping: 16 warps, 4x4 grid of 32x32 tiles
    const int m0 = (w >> 2) * 32, n0 = (w & 3) * 32;
    const int lr = lane >> 2, lq = lane & 3;

    float acc[8][4];
#pragma unroll
    for (int x = 0; x < 8; x++)
#pragma unroll
        for (int y = 0; y < 4; y++) acc[x][y] = 0.f;
    float denp[8];
#pragma unroll
    for (int rr = 0; rr < 8; rr++) denp[rr] = 0.f;

    // prefetch chunk 0 (adj coalesced: 256B contiguous per row)
    int2   mA[8];
    float4 vB[4];
#pragma unroll
    for (int rr = 0; rr < 8; rr++)
        mA[rr] = *(const int2*)(adj + (size_t)(rg0 + wr0 + rr) * N_ + cl);
#pragma unroll
    for (int q = 0; q < 4; q++) vB[q] = whp[q * 8];

    __syncthreads();   // dst_s ready

    for (int c = 0; c < N_ / KC; c++) {
        // ---- weights: exp(lrelu(src+dst+ab)), masked; den in fp32 ----
        float2 dv = *(const float2*)&dst_s[c * KC + cl];
        uint2 wpair[8];
#pragma unroll
        for (int rr = 0; rr < 8; rr++) {
            float e0 = srcA[rr] + dv.x, e1 = srcA[rr] + dv.y;
            e0 = (e0 >= 0.f) ? e0 : 0.01f * e0;
            e1 = (e1 >= 0.f) ? e1 : 0.01f * e1;
            float w0 = (mA[rr].x > 0) ? __expf(e0) : 0.f;
            float w1 = (mA[rr].y > 0) ? __expf(e1) : 0.f;
            denp[rr] += w0 + w1;
            wpair[rr] = make_uint2(f2tf32(w0), f2tf32(w1));
        }

        __syncthreads();   // previous chunk's mma reads done

        // ---- store A (weights) [m][k] and B (Wh) [k][o] ----
#pragma unroll
        for (int rr = 0; rr < 8; rr++)
            *(uint2*)&As[(wr0 + rr) * STRA + cl] = wpair[rr];
#pragma unroll
        for (int q = 0; q < 4; q++)
            *(float4*)&Bs[bj * STRB + (bc + 8 * q) * 4] = vB[q];

        // ---- prefetch next chunk (lands during mma) ----
        if (c < N_ / KC - 1) {
#pragma unroll
            for (int rr = 0; rr < 8; rr++)
                mA[rr] = *(const int2*)(adj + (size_t)(rg0 + wr0 + rr) * N_ + (c + 1) * KC + cl);
#pragma unroll
            for (int q = 0; q < 4; q++)
                vB[q] = whp[(size_t)(c + 1) * KC * (FOUT / 4) + q * 8];
        }

        __syncthreads();

        // ---- mma: 8 k-steps of m16n8k8, 32x32 warp tile ----
#pragma unroll
        for (int kk = 0; kk < 8; kk++) {
            uint32_t bf[4][2];
#pragma unroll
            for (int nt = 0; nt < 4; nt++) {
                int o = n0 + nt * 8 + lr;
                bf[nt][0] = Bs[(kk * 8 + lq) * STRB + o];
                bf[nt][1] = Bs[(kk * 8 + lq + 4) * STRB + o];
            }
#pragma unroll
            for (int mt = 0; mt < 2; mt++) {
                uint32_t af[4];
                int m = m0 + mt * 16 + lr;
                af[0] = As[m * STRA + kk * 8 + lq];
                af[1] = As[(m + 8) * STRA + kk * 8 + lq];
                af[2] = As[m * STRA + kk * 8 + lq + 4];
                af[3] = As[(m + 8) * STRA + kk * 8 + lq + 4];
#pragma unroll
                for (int nt = 0; nt < 4; nt++)
                    mma_tf32(acc[mt * 4 + nt], af, bf[nt]);
            }
        }
    }

    // ---- den: full warp reduce (each row's cols live in one warp) ----
#pragma unroll
    for (int rr = 0; rr < 8; rr++) {
#pragma unroll
        for (int off = 16; off >= 1; off >>= 1)
            denp[rr] += __shfl_xor_sync(0xffffffffu, denp[rr], off);
        if (lane == rr) den_s[wr0 + rr] = denp[rr];
    }
    __syncthreads();

    // ---- epilogue: divide by den, store ----
#pragma unroll
    for (int mt = 0; mt < 2; mt++) {
        int r0 = m0 + mt * 16 + lr;
        int r1 = r0 + 8;
        float inv0 = 1.0f / den_s[r0];
        float inv1 = 1.0f / den_s[r1];
        float* op0 = out + (size_t)(rg0 + r0) * FOUT;
        float* op1 = out + (size_t)(rg0 + r1) * FOUT;
#pragma unroll
        for (int nt = 0; nt < 4; nt++) {
            int col = n0 + nt * 8 + lq * 2;
            *(float2*)(op0 + col) = make_float2(acc[mt * 4 + nt][0] * inv0,
                                                acc[mt * 4 + nt][1] * inv0);
            *(float2*)(op1 + col) = make_float2(acc[mt * 4 + nt][2] * inv1,
                                                acc[mt * 4 + nt][3] * inv1);
        }
    }
}

extern "C" void kernel_launch(void* const* d_in, const int* in_sizes, int n_in,
                              void* d_out, int out_size) {
    const float* h   = (const float*)d_in[0];
    const int*   adj = (const int*)d_in[1];
    const float* Ww  = (const float*)d_in[2];
    const float* Wb  = (const float*)d_in[3];
    const float* aw  = (const float*)d_in[4];
    const float* abp = (const float*)d_in[5];
    float* outp = (float*)d_out;

    cudaFuncSetAttribute(k_attn, cudaFuncAttributeMaxDynamicSharedMemorySize, SMEM_SZ);

    k_gemm<<<MTOT / 64, 256>>>(h, Ww, Wb, aw);
    k_attn<<<MTOT / 128, 512, SMEM_SZ>>>(adj, abp, outp);
}